// round 7
// baseline (speedup 1.0000x reference)
#include <cuda_runtime.h>
#include <cstdint>

#define MM   6
#define BB   128
#define TT   32
#define DINN 64
#define HHH  512
#define EEE  512
#define NEMB 32

#define MAXC      80     // max chunks: (128 + 32)/2
#define ROWS      64     // token rows per block: 2 batches x 32
#define XS_STRIDE 68     // words; mod 32 = 4 -> conflict-free A-fragment LDS
#define HS_STRIDE 516    // words; mod 32 = 4
#define WB_STRIDE 520    // words; mod 32 = 8 -> conflict-free B-fragment LDS
#define SLAB_WORDS (8 * WB_STRIDE)        // one 8k x 512n slab (padded)
#define NSTAGE    4

#define XS_OFF 0
#define HS_OFF (ROWS * XS_STRIDE)                    // 4352
#define WB_OFF (HS_OFF + ROWS * HS_STRIDE)           // 37376
#define SMEM_WORDS (WB_OFF + NSTAGE * SLAB_WORDS)    // 54016 -> 216064 B

// chunk table: (b0, b1) pairs sharing one emb id, grouped by emb
__device__ int g_chunk_b0[MAXC];
__device__ int g_chunk_b1[MAXC];
__device__ int g_chunk_e [MAXC];
__device__ int g_nchunks;

__global__ void pmst_prepass(const int* __restrict__ emb_ids) {
    const int e = threadIdx.x;             // 0..31
    int cnt = 0;
    for (int b = 0; b < BB; b++) cnt += (emb_ids[b] == e);
    int pairs = (cnt + 1) >> 1;
    int off = pairs;
    #pragma unroll
    for (int d = 1; d < 32; d <<= 1) {
        int v = __shfl_up_sync(0xFFFFFFFFu, off, d);
        if (e >= d) off += v;
    }
    if (e == 31) g_nchunks = off;
    int idx = off - pairs;
    int prev = -1;
    for (int b = 0; b < BB; b++) {
        if (emb_ids[b] == e) {
            if (prev < 0) prev = b;
            else { g_chunk_b0[idx] = prev; g_chunk_b1[idx] = b; g_chunk_e[idx] = e; idx++; prev = -1; }
        }
    }
    if (prev >= 0) { g_chunk_b0[idx] = prev; g_chunk_b1[idx] = prev; g_chunk_e[idx] = e; }
}

__device__ __forceinline__ uint32_t f2tf(float f) {
    uint32_t r; asm("cvt.rna.tf32.f32 %0, %1;" : "=r"(r) : "f"(f)); return r;
}

__device__ __forceinline__ void mma8(float* d, const uint32_t* a, const uint32_t* b) {
    asm volatile(
        "mma.sync.aligned.m16n8k8.row.col.f32.tf32.tf32.f32 "
        "{%0,%1,%2,%3}, {%4,%5,%6,%7}, {%8,%9}, {%0,%1,%2,%3};"
        : "+f"(d[0]), "+f"(d[1]), "+f"(d[2]), "+f"(d[3])
        : "r"(a[0]), "r"(a[1]), "r"(a[2]), "r"(a[3]), "r"(b[0]), "r"(b[1]));
}

#define CP_COMMIT() asm volatile("cp.async.commit_group;" ::: "memory")
#define CP_WAIT2()  asm volatile("cp.async.wait_group 2;" ::: "memory")

// Issue one 8x512 f32 slab into stage buffer via cp.async.cg (L1-bypass).
__device__ __forceinline__ void issue_slab(uint32_t wb_addr, int stage,
                                           const float* __restrict__ gsrc, int tid) {
    #pragma unroll
    for (int j = 0; j < 2; j++) {
        const int i = tid + j * 512;           // 0..1023 16B-chunks
        const int row = i >> 7, c4 = i & 127;
        const uint32_t dst = wb_addr + (uint32_t)(stage * SLAB_WORDS + row * WB_STRIDE + c4 * 4) * 4u;
        const float* src = gsrc + (long)row * 512 + c4 * 4;
        asm volatile("cp.async.cg.shared.global [%0], [%1], 16;" :: "r"(dst), "l"(src) : "memory");
    }
}

// grid = (MAXC, MM); block = 512 threads (16 warps). Warp tile: 64 rows x 32 cols.
__global__ __launch_bounds__(512, 1) void pmst_mma_kernel(
    const float* __restrict__ state,   // [B, T, M*DIN]
    const float* __restrict__ W1,      // [M, NEMB, DIN, H]
    const float* __restrict__ b1,      // [M, NEMB, H]
    const float* __restrict__ W2,      // [M, NEMB, H, E]
    const float* __restrict__ b2,      // [M, NEMB, E]
    const float* __restrict__ te,      // [M, E]
    float* __restrict__ out)           // [B, M*T, E]
{
    const int c = blockIdx.x;
    if (c >= g_nchunks) return;
    const int m   = blockIdx.y;
    const int e   = g_chunk_e[c];
    const int b0  = g_chunk_b0[c];
    const int b1v = g_chunk_b1[c];

    extern __shared__ uint32_t smu[];
    uint32_t* Xs = smu + XS_OFF;
    uint32_t* Hs = smu + HS_OFF;
    uint32_t* Wb = smu + WB_OFF;
    uint32_t wb_addr;
    asm("{ .reg .u64 t; cvta.to.shared.u64 t, %1; cvt.u32.u64 %0, t; }"
        : "=r"(wb_addr) : "l"((const void*)Wb));

    const int tid  = threadIdx.x;
    const int wid  = tid >> 5;
    const int lane = tid & 31;
    const int g    = lane >> 2;    // 0..7
    const int tg   = lane & 3;     // 0..3

    const long me = (long)m * NEMB + e;
    const float* W1p = W1 + me * (DINN * HHH);
    const float* W2p = W2 + me * ((long)HHH * EEE);
    const float* b1p = b1 + me * HHH;
    const float* b2p = b2 + me * EEE;
    const float* tep = te + (long)m * EEE;

    const int ncol0 = wid * 32;
    float acc[4][4][4];   // [m-tile 16 rows][n-tile 8 cols][frag]

    // ---- prologue: W1 slabs 0..2 in flight ----
    issue_slab(wb_addr, 0, W1p,            tid); CP_COMMIT();
    issue_slab(wb_addr, 1, W1p +  8 * 512, tid); CP_COMMIT();
    issue_slab(wb_addr, 2, W1p + 16 * 512, tid); CP_COMMIT();

    // ---- stage X (64 rows x 64 k) as tf32 ----
    #pragma unroll
    for (int i = tid; i < ROWS * DINN; i += 512) {
        const int tr = i >> 6, k = i & 63;
        const int bb = (tr < TT) ? b0 : b1v;
        const int t  = tr & (TT - 1);
        Xs[tr * XS_STRIDE + k] =
            f2tf(__ldg(state + ((long)bb * TT + t) * (MM * DINN) + m * DINN + k));
    }

    // ================= GEMM1: H = relu(X @ W1 + b1) =================
    #pragma unroll
    for (int mt = 0; mt < 4; mt++)
        #pragma unroll
        for (int nt = 0; nt < 4; nt++)
            #pragma unroll
            for (int i = 0; i < 4; i++) acc[mt][nt][i] = 0.f;

    for (int kc = 0; kc < 8; kc++) {
        CP_WAIT2();
        __syncthreads();
        if (kc + 3 < 8) issue_slab(wb_addr, (kc + 3) & 3, W1p + (long)(kc + 3) * 8 * 512, tid);
        CP_COMMIT();

        uint32_t a[4][4];
        {
            const uint32_t* xb = Xs + g * XS_STRIDE + tg + kc * 8;
            #pragma unroll
            for (int mt = 0; mt < 4; mt++) {
                const uint32_t* xp = xb + mt * 16 * XS_STRIDE;
                a[mt][0] = xp[0];
                a[mt][1] = xp[8 * XS_STRIDE];
                a[mt][2] = xp[4];
                a[mt][3] = xp[8 * XS_STRIDE + 4];
            }
        }
        const uint32_t* wf = Wb + (kc & 3) * SLAB_WORDS + tg * WB_STRIDE + ncol0 + g;
        #pragma unroll
        for (int nt = 0; nt < 4; nt++) {
            uint32_t bf[2];
            bf[0] = f2tf(__uint_as_float(wf[nt * 8]));
            bf[1] = f2tf(__uint_as_float(wf[4 * WB_STRIDE + nt * 8]));
            #pragma unroll
            for (int mt = 0; mt < 4; mt++) mma8(acc[mt][nt], a[mt], bf);
        }
    }

    // ---- prologue W2 slabs 0..2 (bufs 0-2 safe; overlaps epilogue1) ----
    issue_slab(wb_addr, 0, W2p,            tid); CP_COMMIT();
    issue_slab(wb_addr, 1, W2p +  8 * 512, tid); CP_COMMIT();
    issue_slab(wb_addr, 2, W2p + 16 * 512, tid); CP_COMMIT();

    // ---- epilogue1: relu + bias -> Hs (tf32) ----
    #pragma unroll
    for (int nt = 0; nt < 4; nt++) {
        const int n = ncol0 + nt * 8 + tg * 2;
        const float bb0 = __ldg(b1p + n);
        const float bb1 = __ldg(b1p + n + 1);
        #pragma unroll
        for (int mt = 0; mt < 4; mt++) {
            const int r0 = mt * 16 + g;
            Hs[r0 * HS_STRIDE + n]           = f2tf(fmaxf(acc[mt][nt][0] + bb0, 0.f));
            Hs[r0 * HS_STRIDE + n + 1]       = f2tf(fmaxf(acc[mt][nt][1] + bb1, 0.f));
            Hs[(r0 + 8) * HS_STRIDE + n]     = f2tf(fmaxf(acc[mt][nt][2] + bb0, 0.f));
            Hs[(r0 + 8) * HS_STRIDE + n + 1] = f2tf(fmaxf(acc[mt][nt][3] + bb1, 0.f));
        }
    }

    // ================= GEMM2: Z = H @ W2 + b2 + te =================
    #pragma unroll
    for (int mt = 0; mt < 4; mt++)
        #pragma unroll
        for (int nt = 0; nt < 4; nt++)
            #pragma unroll
            for (int i = 0; i < 4; i++) acc[mt][nt][i] = 0.f;

    for (int kc = 0; kc < 64; kc++) {
        CP_WAIT2();
        __syncthreads();
        if (kc + 3 < 64) issue_slab(wb_addr, (kc + 3) & 3, W2p + (long)(kc + 3) * 8 * 512, tid);
        CP_COMMIT();

        uint32_t a[4][4];
        {
            const uint32_t* hb = Hs + g * HS_STRIDE + tg + kc * 8;
            #pragma unroll
            for (int mt = 0; mt < 4; mt++) {
                const uint32_t* hp = hb + mt * 16 * HS_STRIDE;
                a[mt][0] = hp[0];
                a[mt][1] = hp[8 * HS_STRIDE];
                a[mt][2] = hp[4];
                a[mt][3] = hp[8 * HS_STRIDE + 4];
            }
        }
        const uint32_t* wf = Wb + (kc & 3) * SLAB_WORDS + tg * WB_STRIDE + ncol0 + g;
        #pragma unroll
        for (int nt = 0; nt < 4; nt++) {
            uint32_t bf[2];
            bf[0] = f2tf(__uint_as_float(wf[nt * 8]));
            bf[1] = f2tf(__uint_as_float(wf[4 * WB_STRIDE + nt * 8]));
            #pragma unroll
            for (int mt = 0; mt < 4; mt++) mma8(acc[mt][nt], a[mt], bf);
        }
    }

    // ---- epilogue2: out[b, m*T + t, o] ----
    {
        float* op0 = out + ((long)b0  * MM + m) * TT * EEE;
        float* op1 = out + ((long)b1v * MM + m) * TT * EEE;
        #pragma unroll
        for (int nt = 0; nt < 4; nt++) {
            const int n = ncol0 + nt * 8 + tg * 2;
            const float a0 = __ldg(b2p + n)     + __ldg(tep + n);
            const float a1 = __ldg(b2p + n + 1) + __ldg(tep + n + 1);
            #pragma unroll
            for (int mt = 0; mt < 4; mt++) {
                const int r0 = mt * 16 + g;        // row in [0,64)
                const int r1 = r0 + 8;
                float* p0 = ((r0 < TT) ? op0 : op1) + (long)(r0 & (TT - 1)) * EEE + n;
                float* p1 = ((r1 < TT) ? op0 : op1) + (long)(r1 & (TT - 1)) * EEE + n;
                *(float2*)p0 = make_float2(acc[mt][nt][0] + a0, acc[mt][nt][1] + a1);
                *(float2*)p1 = make_float2(acc[mt][nt][2] + a0, acc[mt][nt][3] + a1);
            }
        }
    }
}

extern "C" void kernel_launch(void* const* d_in, const int* in_sizes, int n_in,
                              void* d_out, int out_size)
{
    const float* state   = (const float*)d_in[0];
    const int*   emb_ids = (const int*)  d_in[1];
    const float* W1      = (const float*)d_in[2];
    const float* b1      = (const float*)d_in[3];
    const float* W2      = (const float*)d_in[4];
    const float* b2      = (const float*)d_in[5];
    const float* te      = (const float*)d_in[6];
    float*       out     = (float*)d_out;

    pmst_prepass<<<1, 32>>>(emb_ids);

    const int smem_bytes = SMEM_WORDS * (int)sizeof(uint32_t); // 216064
    cudaFuncSetAttribute(pmst_mma_kernel,
                         cudaFuncAttributeMaxDynamicSharedMemorySize, smem_bytes);

    dim3 grid(MAXC, MM);
    pmst_mma_kernel<<<grid, 512, smem_bytes>>>(state, W1, b1, W2, b2, te, out);
}

// round 8
// speedup vs baseline: 1.3389x; 1.3389x over previous
#include <cuda_runtime.h>
#include <cstdint>

#define MM   6
#define BB   128
#define TT   32
#define DINN 64
#define HHH  512
#define EEE  512
#define NEMB 32

#define MAXC      80     // max chunks: (128 + 32)/2
#define ROWS      64     // token rows per block: 2 batches x 32
#define XS_STRIDE 68     // words; mod 32 = 4 -> conflict-free A-fragment LDS
#define HS_STRIDE 516    // words; mod 32 = 4

// chunk table: (b0, b1) pairs sharing one emb id, grouped by emb
__device__ int g_chunk_b0[MAXC];
__device__ int g_chunk_b1[MAXC];
__device__ int g_chunk_e [MAXC];
__device__ int g_nchunks;

__global__ void pmst_prepass(const int* __restrict__ emb_ids) {
    const int e = threadIdx.x;             // 0..31
    int cnt = 0;
    for (int b = 0; b < BB; b++) cnt += (emb_ids[b] == e);
    int pairs = (cnt + 1) >> 1;
    int off = pairs;
    #pragma unroll
    for (int d = 1; d < 32; d <<= 1) {
        int v = __shfl_up_sync(0xFFFFFFFFu, off, d);
        if (e >= d) off += v;
    }
    if (e == 31) g_nchunks = off;
    int idx = off - pairs;
    int prev = -1;
    for (int b = 0; b < BB; b++) {
        if (emb_ids[b] == e) {
            if (prev < 0) prev = b;
            else { g_chunk_b0[idx] = prev; g_chunk_b1[idx] = b; g_chunk_e[idx] = e; idx++; prev = -1; }
        }
    }
    if (prev >= 0) { g_chunk_b0[idx] = prev; g_chunk_b1[idx] = prev; g_chunk_e[idx] = e; }
}

__device__ __forceinline__ uint32_t f2tf(float f) {
    uint32_t r; asm("cvt.rna.tf32.f32 %0, %1;" : "=r"(r) : "f"(f)); return r;
}

__device__ __forceinline__ void mma8(float* d, const uint32_t* a, uint32_t b0, uint32_t b1) {
    asm volatile(
        "mma.sync.aligned.m16n8k8.row.col.f32.tf32.tf32.f32 "
        "{%0,%1,%2,%3}, {%4,%5,%6,%7}, {%8,%9}, {%0,%1,%2,%3};"
        : "+f"(d[0]), "+f"(d[1]), "+f"(d[2]), "+f"(d[3])
        : "r"(a[0]), "r"(a[1]), "r"(a[2]), "r"(a[3]), "r"(b0), "r"(b1));
}

// grid = (MAXC, MM); block = 512 threads (16 warps). Warp tile: 64 rows x 32 cols.
// Column permutation: logical mma col (8*nt + j) == physical col (ncol0 + 4*j + nt).
// B-fragment for tile nt at lane (g,tg) = W[k0+tg][ncol0+4g+nt] = component nt of one LDG.128.
__global__ __launch_bounds__(512, 1) void pmst_mma_kernel(
    const float* __restrict__ state,   // [B, T, M*DIN]
    const float* __restrict__ W1,      // [M, NEMB, DIN, H]
    const float* __restrict__ b1,      // [M, NEMB, H]
    const float* __restrict__ W2,      // [M, NEMB, H, E]
    const float* __restrict__ b2,      // [M, NEMB, E]
    const float* __restrict__ te,      // [M, E]
    float* __restrict__ out)           // [B, M*T, E]
{
    const int c = blockIdx.x;
    if (c >= g_nchunks) return;
    const int m   = blockIdx.y;
    const int e   = g_chunk_e[c];
    const int b0  = g_chunk_b0[c];
    const int b1v = g_chunk_b1[c];

    extern __shared__ uint32_t smu[];
    uint32_t* Xs = smu;                        // [ROWS][XS_STRIDE]
    uint32_t* Hs = smu + ROWS * XS_STRIDE;     // [ROWS][HS_STRIDE]

    const int tid  = threadIdx.x;
    const int wid  = tid >> 5;
    const int lane = tid & 31;
    const int g    = lane >> 2;    // 0..7
    const int tg   = lane & 3;     // 0..3

    const long me = (long)m * NEMB + e;
    const float* W1p = W1 + me * (DINN * HHH);
    const float* W2p = W2 + me * ((long)HHH * EEE);
    const float* b1p = b1 + me * HHH;
    const float* b2p = b2 + me * EEE;
    const float* tep = te + (long)m * EEE;

    const int ncol0 = wid * 32;
    float acc[4][4][4];   // [m-tile 16 rows][n-tile][frag]

    // ---- Stage X: 64 rows (2 batches x 32 tokens) as tf32 ----
    #pragma unroll
    for (int i = tid; i < ROWS * DINN; i += 512) {
        const int tr = i >> 6, k = i & 63;
        const int bb = (tr < TT) ? b0 : b1v;
        const int t  = tr & (TT - 1);
        Xs[tr * XS_STRIDE + k] =
            f2tf(__ldg(state + ((long)bb * TT + t) * (MM * DINN) + m * DINN + k));
    }
    __syncthreads();

    // ================= GEMM1: H = relu(X @ W1 + b1) =================
    #pragma unroll
    for (int mt = 0; mt < 4; mt++)
        #pragma unroll
        for (int nt = 0; nt < 4; nt++)
            #pragma unroll
            for (int i = 0; i < 4; i++) acc[mt][nt][i] = 0.f;
    {
        const float* wbase = W1p + (long)tg * HHH + ncol0 + 4 * g;
        float4 v0 = __ldg((const float4*)wbase);
        float4 v1 = __ldg((const float4*)(wbase + 4 * HHH));
        #pragma unroll
        for (int kc = 0; kc < 8; kc++) {
            float4 n0, n1;
            if (kc < 7) {
                const float* p = wbase + (long)(kc + 1) * 8 * HHH;
                n0 = __ldg((const float4*)p);
                n1 = __ldg((const float4*)(p + 4 * HHH));
            }
            uint32_t a[4][4];
            {
                const uint32_t* xb = Xs + g * XS_STRIDE + tg + kc * 8;
                #pragma unroll
                for (int mt = 0; mt < 4; mt++) {
                    const uint32_t* xp = xb + mt * 16 * XS_STRIDE;
                    a[mt][0] = xp[0];
                    a[mt][1] = xp[8 * XS_STRIDE];
                    a[mt][2] = xp[4];
                    a[mt][3] = xp[8 * XS_STRIDE + 4];
                }
            }
            const uint32_t w0[4] = { f2tf(v0.x), f2tf(v0.y), f2tf(v0.z), f2tf(v0.w) };
            const uint32_t w1[4] = { f2tf(v1.x), f2tf(v1.y), f2tf(v1.z), f2tf(v1.w) };
            #pragma unroll
            for (int nt = 0; nt < 4; nt++)
                #pragma unroll
                for (int mt = 0; mt < 4; mt++) mma8(acc[mt][nt], a[mt], w0[nt], w1[nt]);
            v0 = n0; v1 = n1;
        }
    }

    // ---- epilogue1: relu + bias -> Hs at PHYSICAL columns (contiguous per thread) ----
    {
        const int pc = ncol0 + 8 * tg;           // physical col base owned by this thread
        const float4 bL = __ldg((const float4*)(b1p + pc));
        const float4 bH = __ldg((const float4*)(b1p + pc + 4));
        #pragma unroll
        for (int mt = 0; mt < 4; mt++) {
            const int r0 = mt * 16 + g;
            const int r1 = r0 + 8;
            uint4 sl0, sh0, sl1, sh1;
            sl0.x = f2tf(fmaxf(acc[mt][0][0] + bL.x, 0.f));
            sl0.y = f2tf(fmaxf(acc[mt][1][0] + bL.y, 0.f));
            sl0.z = f2tf(fmaxf(acc[mt][2][0] + bL.z, 0.f));
            sl0.w = f2tf(fmaxf(acc[mt][3][0] + bL.w, 0.f));
            sh0.x = f2tf(fmaxf(acc[mt][0][1] + bH.x, 0.f));
            sh0.y = f2tf(fmaxf(acc[mt][1][1] + bH.y, 0.f));
            sh0.z = f2tf(fmaxf(acc[mt][2][1] + bH.z, 0.f));
            sh0.w = f2tf(fmaxf(acc[mt][3][1] + bH.w, 0.f));
            sl1.x = f2tf(fmaxf(acc[mt][0][2] + bL.x, 0.f));
            sl1.y = f2tf(fmaxf(acc[mt][1][2] + bL.y, 0.f));
            sl1.z = f2tf(fmaxf(acc[mt][2][2] + bL.z, 0.f));
            sl1.w = f2tf(fmaxf(acc[mt][3][2] + bL.w, 0.f));
            sh1.x = f2tf(fmaxf(acc[mt][0][3] + bH.x, 0.f));
            sh1.y = f2tf(fmaxf(acc[mt][1][3] + bH.y, 0.f));
            sh1.z = f2tf(fmaxf(acc[mt][2][3] + bH.z, 0.f));
            sh1.w = f2tf(fmaxf(acc[mt][3][3] + bH.w, 0.f));
            *(uint4*)(Hs + r0 * HS_STRIDE + pc)     = sl0;
            *(uint4*)(Hs + r0 * HS_STRIDE + pc + 4) = sh0;
            *(uint4*)(Hs + r1 * HS_STRIDE + pc)     = sl1;
            *(uint4*)(Hs + r1 * HS_STRIDE + pc + 4) = sh1;
        }
    }
    __syncthreads();

    // ================= GEMM2: Z = H @ W2 + b2 + te =================
    #pragma unroll
    for (int mt = 0; mt < 4; mt++)
        #pragma unroll
        for (int nt = 0; nt < 4; nt++)
            #pragma unroll
            for (int i = 0; i < 4; i++) acc[mt][nt][i] = 0.f;
    {
        const float* wbase = W2p + (long)tg * EEE + ncol0 + 4 * g;
        float4 v0 = __ldg((const float4*)wbase);
        float4 v1 = __ldg((const float4*)(wbase + 4 * EEE));
        #pragma unroll 4
        for (int kc = 0; kc < 64; kc++) {
            float4 n0, n1;
            if (kc < 63) {
                const float* p = wbase + (long)(kc + 1) * 8 * EEE;
                n0 = __ldg((const float4*)p);
                n1 = __ldg((const float4*)(p + 4 * EEE));
            }
            uint32_t a[4][4];
            {
                const uint32_t* hb = Hs + g * HS_STRIDE + tg + kc * 8;
                #pragma unroll
                for (int mt = 0; mt < 4; mt++) {
                    const uint32_t* hp = hb + mt * 16 * HS_STRIDE;
                    a[mt][0] = hp[0];
                    a[mt][1] = hp[8 * HS_STRIDE];
                    a[mt][2] = hp[4];
                    a[mt][3] = hp[8 * HS_STRIDE + 4];
                }
            }
            const uint32_t w0[4] = { f2tf(v0.x), f2tf(v0.y), f2tf(v0.z), f2tf(v0.w) };
            const uint32_t w1[4] = { f2tf(v1.x), f2tf(v1.y), f2tf(v1.z), f2tf(v1.w) };
            #pragma unroll
            for (int nt = 0; nt < 4; nt++)
                #pragma unroll
                for (int mt = 0; mt < 4; mt++) mma8(acc[mt][nt], a[mt], w0[nt], w1[nt]);
            v0 = n0; v1 = n1;
        }
    }

    // ---- epilogue2: out[b, m*T + t, physical col] ----
    {
        const int pc = ncol0 + 8 * tg;
        const float4 bL = __ldg((const float4*)(b2p + pc));
        const float4 bH = __ldg((const float4*)(b2p + pc + 4));
        const float4 tL = __ldg((const float4*)(tep + pc));
        const float4 tH = __ldg((const float4*)(tep + pc + 4));
        const float4 aL = make_float4(bL.x + tL.x, bL.y + tL.y, bL.z + tL.z, bL.w + tL.w);
        const float4 aH = make_float4(bH.x + tH.x, bH.y + tH.y, bH.z + tH.z, bH.w + tH.w);
        float* op0 = out + ((long)b0  * MM + m) * TT * EEE;
        float* op1 = out + ((long)b1v * MM + m) * TT * EEE;
        #pragma unroll
        for (int mt = 0; mt < 4; mt++) {
            const int r0 = mt * 16 + g;
            const int r1 = r0 + 8;
            float* p0 = ((r0 < TT) ? op0 : op1) + (long)(r0 & (TT - 1)) * EEE + pc;
            float* p1 = ((r1 < TT) ? op0 : op1) + (long)(r1 & (TT - 1)) * EEE + pc;
            *(float4*)p0 = make_float4(acc[mt][0][0] + aL.x, acc[mt][1][0] + aL.y,
                                       acc[mt][2][0] + aL.z, acc[mt][3][0] + aL.w);
            *(float4*)(p0 + 4) = make_float4(acc[mt][0][1] + aH.x, acc[mt][1][1] + aH.y,
                                             acc[mt][2][1] + aH.z, acc[mt][3][1] + aH.w);
            *(float4*)p1 = make_float4(acc[mt][0][2] + aL.x, acc[mt][1][2] + aL.y,
                                       acc[mt][2][2] + aL.z, acc[mt][3][2] + aL.w);
            *(float4*)(p1 + 4) = make_float4(acc[mt][0][3] + aH.x, acc[mt][1][3] + aH.y,
                                             acc[mt][2][3] + aH.z, acc[mt][3][3] + aH.w);
        }
    }
}

extern "C" void kernel_launch(void* const* d_in, const int* in_sizes, int n_in,
                              void* d_out, int out_size)
{
    const float* state   = (const float*)d_in[0];
    const int*   emb_ids = (const int*)  d_in[1];
    const float* W1      = (const float*)d_in[2];
    const float* b1      = (const float*)d_in[3];
    const float* W2      = (const float*)d_in[4];
    const float* b2      = (const float*)d_in[5];
    const float* te      = (const float*)d_in[6];
    float*       out     = (float*)d_out;

    pmst_prepass<<<1, 32>>>(emb_ids);

    const int smem_bytes = (ROWS * XS_STRIDE + ROWS * HS_STRIDE) * (int)sizeof(uint32_t); // 149504
    cudaFuncSetAttribute(pmst_mma_kernel,
                         cudaFuncAttributeMaxDynamicSharedMemorySize, smem_bytes);

    dim3 grid(MAXC, MM);
    pmst_mma_kernel<<<grid, 512, smem_bytes>>>(state, W1, b1, W2, b2, te, out);
}

// round 9
// speedup vs baseline: 1.7909x; 1.3376x over previous
#include <cuda_runtime.h>
#include <cstdint>

#define MM   6
#define BB   128
#define TT   32
#define DINN 64
#define HHH  512
#define EEE  512
#define NEMB 32

#define MAXC      80
#define ROWS      64     // token rows per block: 2 batches x 32
#define XS_STRIDE 68     // words; mod 32 = 4 -> conflict-free A-fragment LDS
#define HS_STRIDE 516    // words; mod 32 = 4

// weight ring: per-warp, 3 stages x (8 rows x 160B) = 3840 B
#define WROW_B   160
#define WSTG_B   (8 * WROW_B)       // 1280
#define WRING_B  (3 * WSTG_B)       // 3840
#define XS_BYTES (ROWS * XS_STRIDE * 4)              // 17408
#define HS_BYTES (ROWS * HS_STRIDE * 4)              // 132096
#define WR_OFF_B (XS_BYTES + HS_BYTES)               // 149504
#define SMEM_BYTES (WR_OFF_B + 16 * WRING_B)         // 210944

__device__ int g_chunk_b0[MAXC];
__device__ int g_chunk_b1[MAXC];
__device__ int g_chunk_e [MAXC];
__device__ int g_nchunks;

__global__ void pmst_prepass(const int* __restrict__ emb_ids) {
    const int e = threadIdx.x;             // 0..31
    int cnt = 0;
    for (int b = 0; b < BB; b++) cnt += (emb_ids[b] == e);
    int pairs = (cnt + 1) >> 1;
    int off = pairs;
    #pragma unroll
    for (int d = 1; d < 32; d <<= 1) {
        int v = __shfl_up_sync(0xFFFFFFFFu, off, d);
        if (e >= d) off += v;
    }
    if (e == 31) g_nchunks = off;
    int idx = off - pairs;
    int prev = -1;
    for (int b = 0; b < BB; b++) {
        if (emb_ids[b] == e) {
            if (prev < 0) prev = b;
            else { g_chunk_b0[idx] = prev; g_chunk_b1[idx] = b; g_chunk_e[idx] = e; idx++; prev = -1; }
        }
    }
    if (prev >= 0) { g_chunk_b0[idx] = prev; g_chunk_b1[idx] = prev; g_chunk_e[idx] = e; }
}

__device__ __forceinline__ uint32_t f2tf(float f) {
    uint32_t r; asm("cvt.rna.tf32.f32 %0, %1;" : "=r"(r) : "f"(f)); return r;
}

__device__ __forceinline__ void mma8(float* d, const uint32_t* a, uint32_t b0, uint32_t b1) {
    asm volatile(
        "mma.sync.aligned.m16n8k8.row.col.f32.tf32.tf32.f32 "
        "{%0,%1,%2,%3}, {%4,%5,%6,%7}, {%8,%9}, {%0,%1,%2,%3};"
        : "+f"(d[0]), "+f"(d[1]), "+f"(d[2]), "+f"(d[3])
        : "r"(a[0]), "r"(a[1]), "r"(a[2]), "r"(a[3]), "r"(b0), "r"(b1));
}

#define CP_COMMIT() asm volatile("cp.async.commit_group;" ::: "memory")
#define CP_WAIT1()  asm volatile("cp.async.wait_group 1;" ::: "memory")
#define CP_WAIT0()  asm volatile("cp.async.wait_group 0;" ::: "memory")

// Each lane copies exactly the 2x16B it will read back: rows (tg, tg+4), cols 4g..4g+3.
// wrow = W + k0*512 + ncol0 (row k0, this warp's column base).
__device__ __forceinline__ void issue_wslab(uint32_t stage, const float* __restrict__ wrow,
                                            int g, int tg) {
    const float* sA = wrow + (long)tg * 512 + 4 * g;
    const float* sB = sA + 4 * 512;
    const uint32_t dA = stage + (uint32_t)(tg * WROW_B + g * 16);
    const uint32_t dB = dA + 4 * WROW_B;
    asm volatile("cp.async.cg.shared.global [%0], [%1], 16;" :: "r"(dA), "l"(sA) : "memory");
    asm volatile("cp.async.cg.shared.global [%0], [%1], 16;" :: "r"(dB), "l"(sB) : "memory");
}

__device__ __forceinline__ void lds128(float4& v, uint32_t addr) {
    asm volatile("ld.shared.v4.f32 {%0,%1,%2,%3}, [%4];"
                 : "=f"(v.x), "=f"(v.y), "=f"(v.z), "=f"(v.w) : "r"(addr));
}

// grid = (MAXC, MM); block = 512 threads (16 warps). Warp tile: 64 rows x 32 cols.
// Column permutation: logical mma col (8*nt + j) == physical col (ncol0 + 4*j + nt).
__global__ __launch_bounds__(512, 1) void pmst_mma_kernel(
    const float* __restrict__ state,   // [B, T, M*DIN]
    const float* __restrict__ W1,      // [M, NEMB, DIN, H]
    const float* __restrict__ b1,      // [M, NEMB, H]
    const float* __restrict__ W2,      // [M, NEMB, H, E]
    const float* __restrict__ b2,      // [M, NEMB, E]
    const float* __restrict__ te,      // [M, E]
    float* __restrict__ out)           // [B, M*T, E]
{
    const int c = blockIdx.x;
    if (c >= g_nchunks) return;
    const int m   = blockIdx.y;
    const int e   = g_chunk_e[c];
    const int b0  = g_chunk_b0[c];
    const int b1v = g_chunk_b1[c];

    extern __shared__ uint32_t smu[];
    uint32_t* Xs = smu;                        // [ROWS][XS_STRIDE]
    uint32_t* Hs = smu + ROWS * XS_STRIDE;     // [ROWS][HS_STRIDE]
    uint32_t smem_base;
    asm("{ .reg .u64 t; cvta.to.shared.u64 t, %1; cvt.u32.u64 %0, t; }"
        : "=r"(smem_base) : "l"((const void*)smu));

    const int tid  = threadIdx.x;
    const int wid  = tid >> 5;
    const int lane = tid & 31;
    const int g    = lane >> 2;    // 0..7
    const int tg   = lane & 3;     // 0..3

    const uint32_t wring = smem_base + WR_OFF_B + wid * WRING_B;

    const long me = (long)m * NEMB + e;
    const float* W1p = W1 + me * (DINN * HHH);
    const float* W2p = W2 + me * ((long)HHH * EEE);
    const float* b1p = b1 + me * HHH;
    const float* b2p = b2 + me * EEE;
    const float* tep = te + (long)m * EEE;

    const int ncol0 = wid * 32;
    const float* w1base = W1p + ncol0;
    const float* w2base = W2p + ncol0;
    float acc[4][4][4];   // [m-tile 16 rows][n-tile][frag]

    // ---- GEMM1 prologue: stages 0,1 in flight ----
    issue_wslab(wring + 0 * WSTG_B, w1base,            g, tg); CP_COMMIT();
    issue_wslab(wring + 1 * WSTG_B, w1base + 8 * HHH,  g, tg); CP_COMMIT();

    // ---- Stage X: 64 rows (2 batches x 32 tokens) as tf32 ----
    #pragma unroll
    for (int i = tid; i < ROWS * DINN; i += 512) {
        const int tr = i >> 6, k = i & 63;
        const int bb = (tr < TT) ? b0 : b1v;
        const int t  = tr & (TT - 1);
        Xs[tr * XS_STRIDE + k] =
            f2tf(__ldg(state + ((long)bb * TT + t) * (MM * DINN) + m * DINN + k));
    }
    __syncthreads();

    // ================= GEMM1: H = relu(X @ W1 + b1) =================
    #pragma unroll
    for (int mt = 0; mt < 4; mt++)
        #pragma unroll
        for (int nt = 0; nt < 4; nt++)
            #pragma unroll
            for (int i = 0; i < 4; i++) acc[mt][nt][i] = 0.f;

    {
        int stg = 0;
        #pragma unroll
        for (int kc = 0; kc < 8; kc++) {
            CP_WAIT1();
            if (kc + 2 < 8) issue_wslab(wring + ((stg + 2) % 3) * WSTG_B,
                                        w1base + (long)(kc + 2) * 8 * HHH, g, tg);
            CP_COMMIT();

            uint32_t a[4][4];
            {
                const uint32_t* xb = Xs + g * XS_STRIDE + tg + kc * 8;
                #pragma unroll
                for (int mt = 0; mt < 4; mt++) {
                    const uint32_t* xp = xb + mt * 16 * XS_STRIDE;
                    a[mt][0] = xp[0];
                    a[mt][1] = xp[8 * XS_STRIDE];
                    a[mt][2] = xp[4];
                    a[mt][3] = xp[8 * XS_STRIDE + 4];
                }
            }
            float4 v0, v1;
            const uint32_t baseA = wring + stg * WSTG_B + tg * WROW_B + g * 16;
            lds128(v0, baseA);
            lds128(v1, baseA + 4 * WROW_B);
            const uint32_t w0[4] = { f2tf(v0.x), f2tf(v0.y), f2tf(v0.z), f2tf(v0.w) };
            const uint32_t w1f[4] = { f2tf(v1.x), f2tf(v1.y), f2tf(v1.z), f2tf(v1.w) };
            #pragma unroll
            for (int nt = 0; nt < 4; nt++)
                #pragma unroll
                for (int mt = 0; mt < 4; mt++) mma8(acc[mt][nt], a[mt], w0[nt], w1f[nt]);
            stg = (stg + 1) % 3;
        }
    }

    // ---- GEMM2 prologue (overlaps epilogue1 + barrier) ----
    CP_WAIT0();
    issue_wslab(wring + 0 * WSTG_B, w2base,            g, tg); CP_COMMIT();
    issue_wslab(wring + 1 * WSTG_B, w2base + 8 * EEE,  g, tg); CP_COMMIT();

    // ---- epilogue1: relu + bias -> Hs at PHYSICAL columns (contiguous per thread) ----
    {
        const int pc = ncol0 + 8 * tg;
        const float4 bL = __ldg((const float4*)(b1p + pc));
        const float4 bH = __ldg((const float4*)(b1p + pc + 4));
        #pragma unroll
        for (int mt = 0; mt < 4; mt++) {
            const int r0 = mt * 16 + g;
            const int r1 = r0 + 8;
            uint4 sl0, sh0, sl1, sh1;
            sl0.x = f2tf(fmaxf(acc[mt][0][0] + bL.x, 0.f));
            sl0.y = f2tf(fmaxf(acc[mt][1][0] + bL.y, 0.f));
            sl0.z = f2tf(fmaxf(acc[mt][2][0] + bL.z, 0.f));
            sl0.w = f2tf(fmaxf(acc[mt][3][0] + bL.w, 0.f));
            sh0.x = f2tf(fmaxf(acc[mt][0][1] + bH.x, 0.f));
            sh0.y = f2tf(fmaxf(acc[mt][1][1] + bH.y, 0.f));
            sh0.z = f2tf(fmaxf(acc[mt][2][1] + bH.z, 0.f));
            sh0.w = f2tf(fmaxf(acc[mt][3][1] + bH.w, 0.f));
            sl1.x = f2tf(fmaxf(acc[mt][0][2] + bL.x, 0.f));
            sl1.y = f2tf(fmaxf(acc[mt][1][2] + bL.y, 0.f));
            sl1.z = f2tf(fmaxf(acc[mt][2][2] + bL.z, 0.f));
            sl1.w = f2tf(fmaxf(acc[mt][3][2] + bL.w, 0.f));
            sh1.x = f2tf(fmaxf(acc[mt][0][3] + bH.x, 0.f));
            sh1.y = f2tf(fmaxf(acc[mt][1][3] + bH.y, 0.f));
            sh1.z = f2tf(fmaxf(acc[mt][2][3] + bH.z, 0.f));
            sh1.w = f2tf(fmaxf(acc[mt][3][3] + bH.w, 0.f));
            *(uint4*)(Hs + r0 * HS_STRIDE + pc)     = sl0;
            *(uint4*)(Hs + r0 * HS_STRIDE + pc + 4) = sh0;
            *(uint4*)(Hs + r1 * HS_STRIDE + pc)     = sl1;
            *(uint4*)(Hs + r1 * HS_STRIDE + pc + 4) = sh1;
        }
    }
    __syncthreads();

    // ================= GEMM2: Z = H @ W2 + b2 + te =================
    #pragma unroll
    for (int mt = 0; mt < 4; mt++)
        #pragma unroll
        for (int nt = 0; nt < 4; nt++)
            #pragma unroll
            for (int i = 0; i < 4; i++) acc[mt][nt][i] = 0.f;

    {
        int stg = 0;
        #pragma unroll 4
        for (int kc = 0; kc < 64; kc++) {
            CP_WAIT1();
            if (kc + 2 < 64) issue_wslab(wring + ((stg + 2) % 3) * WSTG_B,
                                         w2base + (long)(kc + 2) * 8 * EEE, g, tg);
            CP_COMMIT();

            uint32_t a[4][4];
            {
                const uint32_t* hb = Hs + g * HS_STRIDE + tg + kc * 8;
                #pragma unroll
                for (int mt = 0; mt < 4; mt++) {
                    const uint32_t* hp = hb + mt * 16 * HS_STRIDE;
                    a[mt][0] = hp[0];
                    a[mt][1] = hp[8 * HS_STRIDE];
                    a[mt][2] = hp[4];
                    a[mt][3] = hp[8 * HS_STRIDE + 4];
                }
            }
            float4 v0, v1;
            const uint32_t baseA = wring + stg * WSTG_B + tg * WROW_B + g * 16;
            lds128(v0, baseA);
            lds128(v1, baseA + 4 * WROW_B);
            const uint32_t w0[4] = { f2tf(v0.x), f2tf(v0.y), f2tf(v0.z), f2tf(v0.w) };
            const uint32_t w1f[4] = { f2tf(v1.x), f2tf(v1.y), f2tf(v1.z), f2tf(v1.w) };
            #pragma unroll
            for (int nt = 0; nt < 4; nt++)
                #pragma unroll
                for (int mt = 0; mt < 4; mt++) mma8(acc[mt][nt], a[mt], w0[nt], w1f[nt]);
            stg = (stg + 1) % 3;
        }
    }

    // ---- epilogue2: out[b, m*T + t, physical col] ----
    {
        const int pc = ncol0 + 8 * tg;
        const float4 bL = __ldg((const float4*)(b2p + pc));
        const float4 bH = __ldg((const float4*)(b2p + pc + 4));
        const float4 tL = __ldg((const float4*)(tep + pc));
        const float4 tH = __ldg((const float4*)(tep + pc + 4));
        const float4 aL = make_float4(bL.x + tL.x, bL.y + tL.y, bL.z + tL.z, bL.w + tL.w);
        const float4 aH = make_float4(bH.x + tH.x, bH.y + tH.y, bH.z + tH.z, bH.w + tH.w);
        float* op0 = out + ((long)b0  * MM + m) * TT * EEE;
        float* op1 = out + ((long)b1v * MM + m) * TT * EEE;
        #pragma unroll
        for (int mt = 0; mt < 4; mt++) {
            const int r0 = mt * 16 + g;
            const int r1 = r0 + 8;
            float* p0 = ((r0 < TT) ? op0 : op1) + (long)(r0 & (TT - 1)) * EEE + pc;
            float* p1 = ((r1 < TT) ? op0 : op1) + (long)(r1 & (TT - 1)) * EEE + pc;
            *(float4*)p0 = make_float4(acc[mt][0][0] + aL.x, acc[mt][1][0] + aL.y,
                                       acc[mt][2][0] + aL.z, acc[mt][3][0] + aL.w);
            *(float4*)(p0 + 4) = make_float4(acc[mt][0][1] + aH.x, acc[mt][1][1] + aH.y,
                                             acc[mt][2][1] + aH.z, acc[mt][3][1] + aH.w);
            *(float4*)p1 = make_float4(acc[mt][0][2] + aL.x, acc[mt][1][2] + aL.y,
                                       acc[mt][2][2] + aL.z, acc[mt][3][2] + aL.w);
            *(float4*)(p1 + 4) = make_float4(acc[mt][0][3] + aH.x, acc[mt][1][3] + aH.y,
                                             acc[mt][2][3] + aH.z, acc[mt][3][3] + aH.w);
        }
    }
}

extern "C" void kernel_launch(void* const* d_in, const int* in_sizes, int n_in,
                              void* d_out, int out_size)
{
    const float* state   = (const float*)d_in[0];
    const int*   emb_ids = (const int*)  d_in[1];
    const float* W1      = (const float*)d_in[2];
    const float* b1      = (const float*)d_in[3];
    const float* W2      = (const float*)d_in[4];
    const float* b2      = (const float*)d_in[5];
    const float* te      = (const float*)d_in[6];
    float*       out     = (float*)d_out;

    pmst_prepass<<<1, 32>>>(emb_ids);

    cudaFuncSetAttribute(pmst_mma_kernel,
                         cudaFuncAttributeMaxDynamicSharedMemorySize, SMEM_BYTES);

    dim3 grid(MAXC, MM);
    pmst_mma_kernel<<<grid, 512, SMEM_BYTES>>>(state, W1, b1, W2, b2, te, out);
}